// round 1
// baseline (speedup 1.0000x reference)
#include <cuda_runtime.h>
#include <math.h>

// Problem constants
#define C_DIM 64
#define QK_DIM 32
#define D_DIM 32
#define H_DIM 96
#define W_DIM 96
#define B_DIM 2
#define WT 8          // w-tile per block
#define NT 256        // n = d*8 + w  (32*8)
#define NTHREADS 512

// smem layout (in floats)
#define SXV_OFF   0          // x tile [64][256] (16384), later V as [w][e(stride65)][c] (16640)
#define SXV_SIZE  16640
#define SQ_OFF    16640      // Q [w][d(stride33)][q]  8448
#define SK_OFF    25088      // K  8448
#define SAT_OFF   33536      // attn [w][e(stride33)][d] 8448
#define SW_OFF    41984      // swT [c][129] : 8256
#define SBIAS_OFF 50240      // 128
#define SPOS_OFF  50368      // 1024
#define SMEM_FLOATS 51392
#define SMEM_BYTES (SMEM_FLOATS * 4)
// output staging reuses SQ..SK region: sout[c*257 + n], 64*257=16448 <= 16896 (ends at 33088 < SAT_OFF)

__device__ float g_tb[32];

// ---------------------------------------------------------------------------
// Kernel 0: text bias  tb[q] = mean_t( text_emb @ wt^T )[t,q] + bt[q]
// ---------------------------------------------------------------------------
__global__ void text_bias_kernel(const float* __restrict__ text_emb,
                                 const float* __restrict__ wt,
                                 const float* __restrict__ bt) {
    __shared__ float mcol[256];
    int t = threadIdx.x;
    float s = 0.f;
    #pragma unroll
    for (int r = 0; r < 32; ++r) s += text_emb[r * 256 + t];
    mcol[t] = s * (1.0f / 32.0f);
    __syncthreads();
    int warp = t >> 5, lane = t & 31;
    for (int q = warp; q < 32; q += 8) {
        float acc = 0.f;
        #pragma unroll
        for (int k = 0; k < 8; ++k) acc += wt[q * 256 + lane + k * 32] * mcol[lane + k * 32];
        #pragma unroll
        for (int o = 16; o > 0; o >>= 1) acc += __shfl_xor_sync(0xffffffffu, acc, o);
        if (lane == 0) g_tb[q] = acc + bt[q];
    }
}

// ---------------------------------------------------------------------------
// Main fused kernel: one block per (b, h, w-tile of 8)
// ---------------------------------------------------------------------------
__global__ __launch_bounds__(NTHREADS, 1)
void attn_kernel(const float* __restrict__ x,
                 const float* __restrict__ wq, const float* __restrict__ bq,
                 const float* __restrict__ wk, const float* __restrict__ bk,
                 const float* __restrict__ wv, const float* __restrict__ bv,
                 const float* __restrict__ pos, const float* __restrict__ gamma,
                 float* __restrict__ out) {
    extern __shared__ float sm[];
    float* sxv  = sm + SXV_OFF;
    float* sq   = sm + SQ_OFF;
    float* sk   = sm + SK_OFF;
    float* sat  = sm + SAT_OFF;
    float* swT  = sm + SW_OFF;
    float* sbias = sm + SBIAS_OFF;
    float* spos  = sm + SPOS_OFF;
    float* sout  = sm + SQ_OFF;   // staging reuse

    const int tid = threadIdx.x;
    const int bid = blockIdx.x;
    const int nwT = W_DIM / WT;   // 12
    const int b   = bid / (H_DIM * nwT);
    const int rem = bid % (H_DIM * nwT);
    const int h   = rem / nwT;
    const int w0  = (rem % nwT) * WT;

    const int HW = H_DIM * W_DIM; // 9216
    const size_t base = (size_t)b * C_DIM * D_DIM * HW + (size_t)h * W_DIM + w0;

    // ---- Phase A: loads ----
    #pragma unroll
    for (int it = 0; it < 8; ++it) {
        int i = tid + it * NTHREADS;           // over 4096 float4s
        int c = i >> 6, d = (i >> 1) & 31, w2 = i & 1;
        float4 v = *reinterpret_cast<const float4*>(x + base + ((size_t)c * D_DIM + d) * HW + w2 * 4);
        *reinterpret_cast<float4*>(&sxv[c * 256 + d * 8 + w2 * 4]) = v;
    }
    #pragma unroll
    for (int it = 0; it < 16; ++it) {
        int i = tid + it * NTHREADS;           // 8192 weights
        int o = i >> 6, c = i & 63;
        float wval;
        if (o < 32)       wval = wq[o * 64 + c];
        else if (o < 64)  wval = wk[(o - 32) * 64 + c];
        else              wval = wv[(o - 64) * 64 + c];
        swT[c * 129 + o] = wval;
    }
    if (tid < 128) {
        float bb;
        if (tid < 32)      bb = bq[tid] + g_tb[tid];
        else if (tid < 64) bb = bk[tid - 32] + g_tb[tid - 32];
        else               bb = bv[tid - 64];
        sbias[tid] = bb;
    }
    #pragma unroll
    for (int it = 0; it < 2; ++it) spos[tid + it * NTHREADS] = pos[tid + it * NTHREADS];
    __syncthreads();

    // ---- Phase B: combined GEMM C[128][256] = W[128][64] * X[64][256] ----
    const int warp = tid >> 5, lane = tid & 31;
    const int ow = warp & 3;        // 0:Q 1:K 2,3:V
    const int nw = warp >> 2;
    const int lo = lane & 3;
    const int ln = lane >> 2;
    const int o_base = ow * 32 + lo * 8;
    const int n_base = nw * 64 + ln * 8;

    float acc[8][8];
    #pragma unroll
    for (int j = 0; j < 8; ++j)
        #pragma unroll
        for (int i = 0; i < 8; ++i) acc[j][i] = 0.f;

    #pragma unroll 4
    for (int c = 0; c < 64; ++c) {
        float wr[8];
        #pragma unroll
        for (int j = 0; j < 8; ++j) wr[j] = swT[c * 129 + o_base + j];
        float4 xa = *reinterpret_cast<const float4*>(&sxv[c * 256 + n_base]);
        float4 xb = *reinterpret_cast<const float4*>(&sxv[c * 256 + n_base + 4]);
        float xr[8] = {xa.x, xa.y, xa.z, xa.w, xb.x, xb.y, xb.z, xb.w};
        #pragma unroll
        for (int j = 0; j < 8; ++j)
            #pragma unroll
            for (int i = 0; i < 8; ++i) acc[j][i] = fmaf(wr[j], xr[i], acc[j][i]);
    }

    // Q/K -> smem (attention layout, stride-33 pad, conflict-free)
    if (ow < 2) {
        float* dst = (ow == 0) ? sq : sk;
        #pragma unroll
        for (int j = 0; j < 8; ++j) {
            int o = o_base + j;
            int q = o & 31;
            float bia = sbias[o];
            #pragma unroll
            for (int i = 0; i < 8; ++i) {
                int n = n_base + i;
                int d = n >> 3, w = n & 7;
                dst[w * 1056 + d * 33 + q] = acc[j][i] + bia + spos[q * 32 + d];
            }
        }
    }
    __syncthreads();   // all sxv reads done; V warps may overwrite it

    if (ow >= 2) {
        #pragma unroll
        for (int j = 0; j < 8; ++j) {
            int o = o_base + j;
            float bia = sbias[o];
            int cch = o - 64;
            #pragma unroll
            for (int i = 0; i < 8; ++i) {
                int n = n_base + i;
                int e = n >> 3, w = n & 7;
                sxv[w * 2080 + e * 65 + cch] = acc[j][i] + bia;  // svA[w][e][c]
            }
        }
    }

    // ---- Phase C: scores + softmax, warp = (w, d-half), lane = e ----
    const int aw = warp >> 1;
    const int dh = (warp & 1) * 16;
    float kreg[32];
    #pragma unroll
    for (int q = 0; q < 32; ++q) kreg[q] = sk[aw * 1056 + lane * 33 + q];

    #pragma unroll
    for (int dd = 0; dd < 16; ++dd) {
        int d = dh + dd;
        float s = 0.f;
        #pragma unroll
        for (int q = 0; q < 32; ++q) s = fmaf(sq[aw * 1056 + d * 33 + q], kreg[q], s);
        s *= 0.17677669529663687f;   // 1/sqrt(32)
        float m = s;
        #pragma unroll
        for (int o = 16; o > 0; o >>= 1) m = fmaxf(m, __shfl_xor_sync(0xffffffffu, m, o));
        float ev = __expf(s - m);
        float ssum = ev;
        #pragma unroll
        for (int o = 16; o > 0; o >>= 1) ssum += __shfl_xor_sync(0xffffffffu, ssum, o);
        sat[aw * 1056 + lane * 33 + d] = ev / ssum;   // attn[w][e][d]
    }
    __syncthreads();   // svA + sat complete; sq/sk free for staging

    // ---- Phase D: out[c][d][w] = sum_e attn[d][e] * V[c][e][w] ----
    float oa0[16], oa1[16];
    #pragma unroll
    for (int i = 0; i < 16; ++i) { oa0[i] = 0.f; oa1[i] = 0.f; }
    #pragma unroll
    for (int e = 0; e < 32; ++e) {
        float v0 = sxv[aw * 2080 + e * 65 + lane];
        float v1 = sxv[aw * 2080 + e * 65 + lane + 32];
        #pragma unroll
        for (int i = 0; i < 16; ++i) {
            float a = sat[aw * 1056 + e * 33 + dh + i];
            oa0[i] = fmaf(a, v0, oa0[i]);
            oa1[i] = fmaf(a, v1, oa1[i]);
        }
    }
    // staging sout[c*257 + d*8 + w] (stride-257: conflict-free)
    #pragma unroll
    for (int i = 0; i < 16; ++i) {
        int d = dh + i;
        sout[lane * 257 + d * 8 + aw]        = oa0[i];
        sout[(lane + 32) * 257 + d * 8 + aw] = oa1[i];
    }
    __syncthreads();

    // ---- Epilogue: out = g*attn_out + (1-g)*x, coalesced ----
    const float gm = gamma[0];
    const float g  = 1.f / (1.f + __expf(-gm));
    const float g1 = 1.f - g;
    #pragma unroll
    for (int it = 0; it < 8; ++it) {
        int i = tid + it * NTHREADS;
        int c = i >> 6, d = (i >> 1) & 31, w2 = i & 1;
        size_t gaddr = base + ((size_t)c * D_DIM + d) * HW + w2 * 4;
        float4 xv = *reinterpret_cast<const float4*>(x + gaddr);
        const float* sp = &sout[c * 257 + d * 8 + w2 * 4];
        float4 r;
        r.x = g * sp[0] + g1 * xv.x;
        r.y = g * sp[1] + g1 * xv.y;
        r.z = g * sp[2] + g1 * xv.z;
        r.w = g * sp[3] + g1 * xv.w;
        *reinterpret_cast<float4*>(out + gaddr) = r;
    }
}

// ---------------------------------------------------------------------------
extern "C" void kernel_launch(void* const* d_in, const int* in_sizes, int n_in,
                              void* d_out, int out_size) {
    const float* x        = (const float*)d_in[0];
    const float* text_emb = (const float*)d_in[1];
    const float* wq       = (const float*)d_in[2];
    const float* bq       = (const float*)d_in[3];
    const float* wk       = (const float*)d_in[4];
    const float* bk       = (const float*)d_in[5];
    const float* wv       = (const float*)d_in[6];
    const float* bv       = (const float*)d_in[7];
    const float* wt       = (const float*)d_in[8];
    const float* bt       = (const float*)d_in[9];
    const float* pos      = (const float*)d_in[10];
    const float* gamma    = (const float*)d_in[11];
    float* out = (float*)d_out;

    cudaFuncSetAttribute(attn_kernel, cudaFuncAttributeMaxDynamicSharedMemorySize, SMEM_BYTES);

    text_bias_kernel<<<1, 256>>>(text_emb, wt, bt);

    const int grid = B_DIM * H_DIM * (W_DIM / WT);  // 2304
    attn_kernel<<<grid, NTHREADS, SMEM_BYTES>>>(x, wq, bq, wk, bk, wv, bv, pos, gamma, out);
}

// round 2
// speedup vs baseline: 1.0251x; 1.0251x over previous
#include <cuda_runtime.h>
#include <math.h>

// Problem constants
#define C_DIM 64
#define QK_DIM 32
#define D_DIM 32
#define H_DIM 96
#define W_DIM 96
#define B_DIM 2
#define WT 8          // w-tile per block
#define NT 256        // n = d*8 + w  (32*8)
#define NTHREADS 512

// smem layout (in floats)
#define SXV_OFF   0          // x tile [64][256] (16384), later V as [w][e(stride65)][c] (16640)
#define SQ_OFF    16640      // Q [w][d(stride33)][q]  8448
#define SK_OFF    25088      // K  8448
#define SAT_OFF   33536      // attn [w][e(stride34)][d] 8704 (even stride -> u64-aligned reads)
#define SW_OFF    42240      // swT [c][132] : 8448 (16B-aligned rows for LDS.128)
#define SBIAS_OFF 50688      // 128
#define SPOS_OFF  50816      // 1024
#define SMEM_FLOATS 51840
#define SMEM_BYTES (SMEM_FLOATS * 4)
// output staging reuses SQ..SK region: sout[c*257 + n], 64*257=16448 <= 16896

__device__ float g_tb[32];

// ---- packed f32x2 helpers (FFMA2 path, ptxas never auto-fuses) ----
__device__ __forceinline__ unsigned long long pk(float a, float b) {
    unsigned long long r;
    asm("mov.b64 %0, {%1, %2};" : "=l"(r) : "f"(a), "f"(b));
    return r;
}
__device__ __forceinline__ void upk(unsigned long long v, float& a, float& b) {
    asm("mov.b64 {%0, %1}, %2;" : "=f"(a), "=f"(b) : "l"(v));
}
__device__ __forceinline__ unsigned long long fma2(unsigned long long a, unsigned long long b,
                                                   unsigned long long c) {
    unsigned long long d;
    asm("fma.rn.f32x2 %0, %1, %2, %3;" : "=l"(d) : "l"(a), "l"(b), "l"(c));
    return d;
}

// ---------------------------------------------------------------------------
// Kernel 0: text bias  tb[q] = mean_t( text_emb @ wt^T )[t,q] + bt[q]
// ---------------------------------------------------------------------------
__global__ void text_bias_kernel(const float* __restrict__ text_emb,
                                 const float* __restrict__ wt,
                                 const float* __restrict__ bt) {
    __shared__ float mcol[256];
    int t = threadIdx.x;
    float s = 0.f;
    #pragma unroll
    for (int r = 0; r < 32; ++r) s += text_emb[r * 256 + t];
    mcol[t] = s * (1.0f / 32.0f);
    __syncthreads();
    int warp = t >> 5, lane = t & 31;
    for (int q = warp; q < 32; q += 8) {
        float acc = 0.f;
        #pragma unroll
        for (int k = 0; k < 8; ++k) acc += wt[q * 256 + lane + k * 32] * mcol[lane + k * 32];
        #pragma unroll
        for (int o = 16; o > 0; o >>= 1) acc += __shfl_xor_sync(0xffffffffu, acc, o);
        if (lane == 0) g_tb[q] = acc + bt[q];
    }
}

// ---------------------------------------------------------------------------
// Main fused kernel: one block per (b, h, w-tile of 8)
// ---------------------------------------------------------------------------
__global__ __launch_bounds__(NTHREADS, 1)
void attn_kernel(const float* __restrict__ x,
                 const float* __restrict__ wq, const float* __restrict__ bq,
                 const float* __restrict__ wk, const float* __restrict__ bk,
                 const float* __restrict__ wv, const float* __restrict__ bv,
                 const float* __restrict__ pos, const float* __restrict__ gamma,
                 float* __restrict__ out) {
    extern __shared__ float sm[];
    float* sxv  = sm + SXV_OFF;
    float* sq   = sm + SQ_OFF;
    float* sk   = sm + SK_OFF;
    float* sat  = sm + SAT_OFF;
    float* swT  = sm + SW_OFF;
    float* sbias = sm + SBIAS_OFF;
    float* spos  = sm + SPOS_OFF;
    float* sout  = sm + SQ_OFF;   // staging reuse

    const int tid = threadIdx.x;
    const int bid = blockIdx.x;
    const int nwT = W_DIM / WT;   // 12
    const int b   = bid / (H_DIM * nwT);
    const int rem = bid % (H_DIM * nwT);
    const int h   = rem / nwT;
    const int w0  = (rem % nwT) * WT;

    const int HW = H_DIM * W_DIM; // 9216
    const size_t base = (size_t)b * C_DIM * D_DIM * HW + (size_t)h * W_DIM + w0;

    // ---- Phase A: loads ----
    #pragma unroll
    for (int it = 0; it < 8; ++it) {
        int i = tid + it * NTHREADS;           // over 4096 float4s
        int c = i >> 6, d = (i >> 1) & 31, w2 = i & 1;
        float4 v = *reinterpret_cast<const float4*>(x + base + ((size_t)c * D_DIM + d) * HW + w2 * 4);
        *reinterpret_cast<float4*>(&sxv[c * 256 + d * 8 + w2 * 4]) = v;
    }
    #pragma unroll
    for (int it = 0; it < 16; ++it) {
        int i = tid + it * NTHREADS;           // 8192 weights
        int o = i >> 6, c = i & 63;
        float wval;
        if (o < 32)       wval = wq[o * 64 + c];
        else if (o < 64)  wval = wk[(o - 32) * 64 + c];
        else              wval = wv[(o - 64) * 64 + c];
        swT[c * 132 + o] = wval;
    }
    if (tid < 128) {
        float bb;
        if (tid < 32)      bb = bq[tid] + g_tb[tid];
        else if (tid < 64) bb = bk[tid - 32] + g_tb[tid - 32];
        else               bb = bv[tid - 64];
        sbias[tid] = bb;
    }
    #pragma unroll
    for (int it = 0; it < 2; ++it) spos[tid + it * NTHREADS] = pos[tid + it * NTHREADS];
    __syncthreads();

    // ---- Phase B: combined GEMM C[128][256] = W[128][64] * X[64][256], FFMA2 ----
    const int warp = tid >> 5, lane = tid & 31;
    const int ow = warp & 3;        // 0:Q 1:K 2,3:V
    const int nw = warp >> 2;
    const int lo = lane & 3;
    const int ln = lane >> 2;
    const int o_base = ow * 32 + lo * 8;
    const int n_base = nw * 64 + ln * 8;

    unsigned long long acc[8][4];
    #pragma unroll
    for (int j = 0; j < 8; ++j)
        #pragma unroll
        for (int i = 0; i < 4; ++i) acc[j][i] = 0ull;

    #pragma unroll 4
    for (int c = 0; c < 64; ++c) {
        float4 wv0 = *reinterpret_cast<const float4*>(&swT[c * 132 + o_base]);
        float4 wv1 = *reinterpret_cast<const float4*>(&swT[c * 132 + o_base + 4]);
        float4 xa = *reinterpret_cast<const float4*>(&sxv[c * 256 + n_base]);
        float4 xb = *reinterpret_cast<const float4*>(&sxv[c * 256 + n_base + 4]);
        unsigned long long xp[4] = { pk(xa.x, xa.y), pk(xa.z, xa.w),
                                     pk(xb.x, xb.y), pk(xb.z, xb.w) };
        float wr[8] = {wv0.x, wv0.y, wv0.z, wv0.w, wv1.x, wv1.y, wv1.z, wv1.w};
        #pragma unroll
        for (int j = 0; j < 8; ++j) {
            unsigned long long wd = pk(wr[j], wr[j]);
            #pragma unroll
            for (int i = 0; i < 4; ++i) acc[j][i] = fma2(wd, xp[i], acc[j][i]);
        }
    }

    // Q/K -> smem (attention layout, stride-33 pad, conflict-free)
    if (ow < 2) {
        float* dst = (ow == 0) ? sq : sk;
        const int d = n_base >> 3;        // same d for the whole 8-wide n range
        #pragma unroll
        for (int j = 0; j < 8; ++j) {
            int o = o_base + j;
            int q = o & 31;
            float bq_ = sbias[o] + spos[q * 32 + d];
            #pragma unroll
            for (int ip = 0; ip < 4; ++ip) {
                float vlo, vhi; upk(acc[j][ip], vlo, vhi);
                dst[(2 * ip) * 1056 + d * 33 + q]     = vlo + bq_;
                dst[(2 * ip + 1) * 1056 + d * 33 + q] = vhi + bq_;
            }
        }
    }
    __syncthreads();   // all sxv reads done; V warps may overwrite it

    if (ow >= 2) {
        const int e = n_base >> 3;
        #pragma unroll
        for (int j = 0; j < 8; ++j) {
            int o = o_base + j;
            float bia = sbias[o];
            int cch = o - 64;
            #pragma unroll
            for (int ip = 0; ip < 4; ++ip) {
                float vlo, vhi; upk(acc[j][ip], vlo, vhi);
                sxv[(2 * ip) * 2080 + e * 65 + cch]     = vlo + bia;  // svA[w][e][c]
                sxv[(2 * ip + 1) * 2080 + e * 65 + cch] = vhi + bia;
            }
        }
    }

    // ---- Phase C: scores + softmax, warp = (w, d-half), lane = e ----
    const int aw = warp >> 1;
    const int dh = (warp & 1) * 16;
    const float* krow = &sk[aw * 1056 + lane * 33];
    unsigned long long kp[16];
    #pragma unroll
    for (int qq = 0; qq < 16; ++qq) kp[qq] = pk(krow[2 * qq], krow[2 * qq + 1]);

    #pragma unroll
    for (int dd = 0; dd < 16; ++dd) {
        int d = dh + dd;
        const float* qr = &sq[aw * 1056 + d * 33];
        unsigned long long s0 = 0ull, s1 = 0ull;
        #pragma unroll
        for (int qq = 0; qq < 8; ++qq) {
            s0 = fma2(pk(qr[4 * qq],     qr[4 * qq + 1]), kp[2 * qq],     s0);
            s1 = fma2(pk(qr[4 * qq + 2], qr[4 * qq + 3]), kp[2 * qq + 1], s1);
        }
        float a0, b0, a1, b1; upk(s0, a0, b0); upk(s1, a1, b1);
        float s = ((a0 + a1) + (b0 + b1)) * 0.17677669529663687f;   // 1/sqrt(32)
        float m = s;
        #pragma unroll
        for (int o = 16; o > 0; o >>= 1) m = fmaxf(m, __shfl_xor_sync(0xffffffffu, m, o));
        float ev = __expf(s - m);
        float ssum = ev;
        #pragma unroll
        for (int o = 16; o > 0; o >>= 1) ssum += __shfl_xor_sync(0xffffffffu, ssum, o);
        sat[aw * 1088 + lane * 34 + d] = __fdividef(ev, ssum);   // attn[w][e][d]
    }
    __syncthreads();   // svA + sat complete; sq/sk free for staging

    // ---- Phase D: out[c][d][w] = sum_e attn[d][e] * V[c][e][w], packed over d ----
    unsigned long long acc0[8], acc1[8];
    #pragma unroll
    for (int i = 0; i < 8; ++i) { acc0[i] = 0ull; acc1[i] = 0ull; }
    const float* vbase = &sxv[aw * 2080];
    #pragma unroll
    for (int e = 0; e < 32; ++e) {
        float v0 = vbase[e * 65 + lane];
        float v1 = vbase[e * 65 + lane + 32];
        unsigned long long v0p = pk(v0, v0);
        unsigned long long v1p = pk(v1, v1);
        const unsigned long long* ap =
            reinterpret_cast<const unsigned long long*>(&sat[aw * 1088 + e * 34 + dh]);
        #pragma unroll
        for (int i = 0; i < 8; ++i) {
            unsigned long long a = ap[i];
            acc0[i] = fma2(a, v0p, acc0[i]);
            acc1[i] = fma2(a, v1p, acc1[i]);
        }
    }
    // staging sout[c*257 + d*8 + w] (stride-257: conflict-free)
    #pragma unroll
    for (int i = 0; i < 8; ++i) {
        float vlo, vhi;
        upk(acc0[i], vlo, vhi);
        sout[lane * 257 + (dh + 2 * i) * 8 + aw]     = vlo;
        sout[lane * 257 + (dh + 2 * i + 1) * 8 + aw] = vhi;
        upk(acc1[i], vlo, vhi);
        sout[(lane + 32) * 257 + (dh + 2 * i) * 8 + aw]     = vlo;
        sout[(lane + 32) * 257 + (dh + 2 * i + 1) * 8 + aw] = vhi;
    }
    __syncthreads();

    // ---- Epilogue: out = g*attn_out + (1-g)*x, coalesced ----
    const float gm = gamma[0];
    const float g  = 1.f / (1.f + __expf(-gm));
    const float g1 = 1.f - g;
    #pragma unroll
    for (int it = 0; it < 8; ++it) {
        int i = tid + it * NTHREADS;
        int c = i >> 6, d = (i >> 1) & 31, w2 = i & 1;
        size_t gaddr = base + ((size_t)c * D_DIM + d) * HW + w2 * 4;
        float4 xv = *reinterpret_cast<const float4*>(x + gaddr);
        const float* sp = &sout[c * 257 + d * 8 + w2 * 4];
        float4 r;
        r.x = g * sp[0] + g1 * xv.x;
        r.y = g * sp[1] + g1 * xv.y;
        r.z = g * sp[2] + g1 * xv.z;
        r.w = g * sp[3] + g1 * xv.w;
        *reinterpret_cast<float4*>(out + gaddr) = r;
    }
}

// ---------------------------------------------------------------------------
extern "C" void kernel_launch(void* const* d_in, const int* in_sizes, int n_in,
                              void* d_out, int out_size) {
    const float* x        = (const float*)d_in[0];
    const float* text_emb = (const float*)d_in[1];
    const float* wq       = (const float*)d_in[2];
    const float* bq       = (const float*)d_in[3];
    const float* wk       = (const float*)d_in[4];
    const float* bk       = (const float*)d_in[5];
    const float* wv       = (const float*)d_in[6];
    const float* bv       = (const float*)d_in[7];
    const float* wt       = (const float*)d_in[8];
    const float* bt       = (const float*)d_in[9];
    const float* pos      = (const float*)d_in[10];
    const float* gamma    = (const float*)d_in[11];
    float* out = (float*)d_out;

    cudaFuncSetAttribute(attn_kernel, cudaFuncAttributeMaxDynamicSharedMemorySize, SMEM_BYTES);

    text_bias_kernel<<<1, 256>>>(text_emb, wt, bt);

    const int grid = B_DIM * H_DIM * (W_DIM / WT);  // 2304
    attn_kernel<<<grid, NTHREADS, SMEM_BYTES>>>(x, wq, bq, wk, bk, wv, bv, pos, gamma, out);
}

// round 3
// speedup vs baseline: 1.1648x; 1.1362x over previous
#include <cuda_runtime.h>
#include <math.h>
#include <stdint.h>

// Problem constants
#define C_DIM 64
#define QK_DIM 32
#define D_DIM 32
#define H_DIM 96
#define W_DIM 96
#define B_DIM 2
#define WT 8          // w-tile per block
#define NTHREADS 512

// smem layout (floats)
#define SXV_OFF   0          // x tile [64][264] tf32 (16896); later V [w][e(65)][c] (16640)
#define SQ_OFF    16896      // Q [w][d(33)][q] 8448
#define SK_OFF    25344      // K 8448
#define SAT_OFF   33792      // attn [w][e(33)][d] 8448
#define SAW_OFF   42240      // prepacked W A-fragments: 8*8*32*4 = 8192
#define SBIAS_OFF 50432      // 128
#define SPOS_OFF  50560      // 1024
#define SMEM_FLOATS 51584
#define SMEM_BYTES (SMEM_FLOATS * 4)
// output staging reuses SQ..SK region: sout[c*257 + n], 64*257=16448 <= 16896

__device__ float g_tb[32];

__device__ __forceinline__ float tf32r(float x) {
    uint32_t u;
    asm("cvt.rna.tf32.f32 %0, %1;" : "=r"(u) : "f"(x));
    return __uint_as_float(u);
}

__device__ __forceinline__ void mma_tf32(float* d, const float4& a, uint32_t b0, uint32_t b1) {
    const uint32_t* A = reinterpret_cast<const uint32_t*>(&a);
    asm volatile(
        "mma.sync.aligned.m16n8k8.row.col.f32.tf32.tf32.f32 "
        "{%0,%1,%2,%3}, {%4,%5,%6,%7}, {%8,%9}, {%0,%1,%2,%3};"
        : "+f"(d[0]), "+f"(d[1]), "+f"(d[2]), "+f"(d[3])
        : "r"(A[0]), "r"(A[1]), "r"(A[2]), "r"(A[3]), "r"(b0), "r"(b1));
}

// ---------------------------------------------------------------------------
// Kernel 0: text bias  tb[q] = mean_t( text_emb @ wt^T )[t,q] + bt[q]
// ---------------------------------------------------------------------------
__global__ void text_bias_kernel(const float* __restrict__ text_emb,
                                 const float* __restrict__ wt,
                                 const float* __restrict__ bt) {
    __shared__ float mcol[256];
    int t = threadIdx.x;
    float s = 0.f;
    #pragma unroll
    for (int r = 0; r < 32; ++r) s += text_emb[r * 256 + t];
    mcol[t] = s * (1.0f / 32.0f);
    __syncthreads();
    int warp = t >> 5, lane = t & 31;
    for (int q = warp; q < 32; q += 8) {
        float acc = 0.f;
        #pragma unroll
        for (int k = 0; k < 8; ++k) acc += wt[q * 256 + lane + k * 32] * mcol[lane + k * 32];
        #pragma unroll
        for (int o = 16; o > 0; o >>= 1) acc += __shfl_xor_sync(0xffffffffu, acc, o);
        if (lane == 0) g_tb[q] = acc + bt[q];
    }
}

// ---------------------------------------------------------------------------
// Main fused kernel: one block per (b, h, w-tile of 8)
// ---------------------------------------------------------------------------
__global__ __launch_bounds__(NTHREADS, 1)
void attn_kernel(const float* __restrict__ x,
                 const float* __restrict__ wq, const float* __restrict__ bq,
                 const float* __restrict__ wk, const float* __restrict__ bk,
                 const float* __restrict__ wv, const float* __restrict__ bv,
                 const float* __restrict__ pos, const float* __restrict__ gamma,
                 float* __restrict__ out) {
    extern __shared__ float sm[];
    float* sxv   = sm + SXV_OFF;
    float* sq    = sm + SQ_OFF;
    float* sk    = sm + SK_OFF;
    float* sat   = sm + SAT_OFF;
    float* saw   = sm + SAW_OFF;
    float* sbias = sm + SBIAS_OFF;
    float* spos  = sm + SPOS_OFF;
    float* sout  = sm + SQ_OFF;   // staging reuse

    const int tid = threadIdx.x;
    const int bid = blockIdx.x;
    const int nwT = W_DIM / WT;   // 12
    const int b   = bid / (H_DIM * nwT);
    const int rem = bid % (H_DIM * nwT);
    const int h   = rem / nwT;
    const int w0  = (rem % nwT) * WT;

    const int HW = H_DIM * W_DIM; // 9216
    const size_t base = (size_t)b * C_DIM * D_DIM * HW + (size_t)h * W_DIM + w0;

    // ---- Phase A: loads ----
    // x tile -> sxv[c*264 + d*8 + w2*4], tf32-rounded
    #pragma unroll
    for (int it = 0; it < 8; ++it) {
        int i = tid + it * NTHREADS;           // 4096 float4s
        int c = i >> 6, d = (i >> 1) & 31, w2 = i & 1;
        float4 v = *reinterpret_cast<const float4*>(x + base + ((size_t)c * D_DIM + d) * HW + w2 * 4);
        v.x = tf32r(v.x); v.y = tf32r(v.y); v.z = tf32r(v.z); v.w = tf32r(v.w);
        *reinterpret_cast<float4*>(&sxv[c * 264 + d * 8 + w2 * 4]) = v;
    }
    // W prepacked into A-fragment order:
    // saw[((mt*8+kt)*32 + lane)*4 + v] = W[mt*16 + g + (v&1)*8][kt*8 + t + (v>>1)*4]
    #pragma unroll
    for (int it = 0; it < 16; ++it) {
        int idx = tid + it * NTHREADS;         // 8192 elems
        int v    = idx & 3;
        int lane = (idx >> 2) & 31;
        int kt   = (idx >> 7) & 7;
        int mt   = idx >> 10;
        int g = lane >> 2, t = lane & 3;
        int o = mt * 16 + g + (v & 1) * 8;
        int c = kt * 8 + t + (v >> 1) * 4;
        float wval;
        if (o < 32)       wval = wq[o * 64 + c];
        else if (o < 64)  wval = wk[(o - 32) * 64 + c];
        else              wval = wv[(o - 64) * 64 + c];
        saw[idx] = tf32r(wval);
    }
    if (tid < 128) {
        float bb;
        if (tid < 32)      bb = bq[tid] + g_tb[tid];
        else if (tid < 64) bb = bk[tid - 32] + g_tb[tid - 32];
        else               bb = bv[tid - 64];
        sbias[tid] = bb;
    }
    #pragma unroll
    for (int it = 0; it < 2; ++it) spos[tid + it * NTHREADS] = pos[tid + it * NTHREADS];
    __syncthreads();

    // ---- Phase B: tf32 MMA GEMM  C[128 o][256 n] = W[128,64] * X[64,256] ----
    const int warp = tid >> 5, lane = tid & 31;
    const int mw = warp & 3;        // 0:Q 1:K 2:V(c0-31) 3:V(c32-63)
    const int nw = warp >> 2;       // n quarter (64 wide)
    const int g = lane >> 2, t = lane & 3;

    float acc[2][8][4];
    #pragma unroll
    for (int s_ = 0; s_ < 2; ++s_)
        #pragma unroll
        for (int nt = 0; nt < 8; ++nt)
            #pragma unroll
            for (int v = 0; v < 4; ++v) acc[s_][nt][v] = 0.f;

    #pragma unroll
    for (int kt = 0; kt < 8; ++kt) {
        float4 a0 = *reinterpret_cast<const float4*>(&saw[((mw * 2 + 0) * 8 + kt) * 128 + lane * 4]);
        float4 a1 = *reinterpret_cast<const float4*>(&saw[((mw * 2 + 1) * 8 + kt) * 128 + lane * 4]);
        const float* xb0 = &sxv[(kt * 8 + t) * 264 + nw * 64 + g];
        const float* xb1 = &sxv[(kt * 8 + t + 4) * 264 + nw * 64 + g];
        #pragma unroll
        for (int nt = 0; nt < 8; ++nt) {
            uint32_t b0 = __float_as_uint(xb0[nt * 8]);
            uint32_t b1 = __float_as_uint(xb1[nt * 8]);
            mma_tf32(acc[0][nt], a0, b0, b1);
            mma_tf32(acc[1][nt], a1, b0, b1);
        }
    }

    // Q/K epilogue -> sq/sk[w*1056 + d*33 + q]
    if (mw < 2) {
        float* dst = (mw == 0) ? sq : sk;
        #pragma unroll
        for (int s_ = 0; s_ < 2; ++s_) {
            #pragma unroll
            for (int nt = 0; nt < 8; ++nt) {
                int d = nw * 8 + nt;
                #pragma unroll
                for (int v = 0; v < 4; ++v) {
                    int q = s_ * 16 + g + (v >> 1) * 8;     // C-frag: row+8 when v>=2
                    int w = 2 * t + (v & 1);                //         col+1 when v odd
                    dst[w * 1056 + d * 33 + q] =
                        acc[s_][nt][v] + sbias[mw * 32 + q] + spos[q * 32 + d];
                }
            }
        }
    }
    __syncthreads();   // all X reads done; V warps may overwrite sxv

    if (mw >= 2) {
        #pragma unroll
        for (int s_ = 0; s_ < 2; ++s_) {
            #pragma unroll
            for (int nt = 0; nt < 8; ++nt) {
                int e = nw * 8 + nt;
                #pragma unroll
                for (int v = 0; v < 4; ++v) {
                    int cch = (mw - 2) * 32 + s_ * 16 + g + (v >> 1) * 8;
                    int w = 2 * t + (v & 1);
                    sxv[w * 2080 + e * 65 + cch] = acc[s_][nt][v] + sbias[64 + cch];
                }
            }
        }
    }

    // ---- Phase C: scores + softmax, warp = (w, d-half), lane = e ----
    const int aw = warp >> 1;
    const int dh = (warp & 1) * 16;
    float kreg[32];
    #pragma unroll
    for (int q = 0; q < 32; ++q) kreg[q] = sk[aw * 1056 + lane * 33 + q];

    #pragma unroll
    for (int dd = 0; dd < 16; ++dd) {
        int d = dh + dd;
        float s = 0.f;
        #pragma unroll
        for (int q = 0; q < 32; ++q) s = fmaf(sq[aw * 1056 + d * 33 + q], kreg[q], s);
        s *= 0.17677669529663687f;   // 1/sqrt(32)
        float m = s;
        #pragma unroll
        for (int o = 16; o > 0; o >>= 1) m = fmaxf(m, __shfl_xor_sync(0xffffffffu, m, o));
        float ev = __expf(s - m);
        float ssum = ev;
        #pragma unroll
        for (int o = 16; o > 0; o >>= 1) ssum += __shfl_xor_sync(0xffffffffu, ssum, o);
        sat[aw * 1056 + lane * 33 + d] = __fdividef(ev, ssum);   // attn[w][e][d]
    }
    __syncthreads();   // V + sat complete; sq/sk free for staging

    // ---- Phase D: out[c][d][w] = sum_e attn[d][e] * V[c][e][w] ----
    float oa0[16], oa1[16];
    #pragma unroll
    for (int i = 0; i < 16; ++i) { oa0[i] = 0.f; oa1[i] = 0.f; }
    const float* vbase = &sxv[aw * 2080];
    #pragma unroll
    for (int e = 0; e < 32; ++e) {
        float v0 = vbase[e * 65 + lane];
        float v1 = vbase[e * 65 + lane + 32];
        const float* ap = &sat[aw * 1056 + e * 33 + dh];
        #pragma unroll
        for (int i = 0; i < 16; ++i) {
            float a = ap[i];
            oa0[i] = fmaf(a, v0, oa0[i]);
            oa1[i] = fmaf(a, v1, oa1[i]);
        }
    }
    // staging sout[c*257 + d*8 + w]
    #pragma unroll
    for (int i = 0; i < 16; ++i) {
        int d = dh + i;
        sout[lane * 257 + d * 8 + aw]        = oa0[i];
        sout[(lane + 32) * 257 + d * 8 + aw] = oa1[i];
    }
    __syncthreads();

    // ---- Epilogue: out = g*attn_out + (1-g)*x, coalesced ----
    const float gm = gamma[0];
    const float g_  = 1.f / (1.f + __expf(-gm));
    const float g1 = 1.f - g_;
    #pragma unroll
    for (int it = 0; it < 8; ++it) {
        int i = tid + it * NTHREADS;
        int c = i >> 6, d = (i >> 1) & 31, w2 = i & 1;
        size_t gaddr = base + ((size_t)c * D_DIM + d) * HW + w2 * 4;
        float4 xv = *reinterpret_cast<const float4*>(x + gaddr);
        const float* sp = &sout[c * 257 + d * 8 + w2 * 4];
        float4 r;
        r.x = g_ * sp[0] + g1 * xv.x;
        r.y = g_ * sp[1] + g1 * xv.y;
        r.z = g_ * sp[2] + g1 * xv.z;
        r.w = g_ * sp[3] + g1 * xv.w;
        *reinterpret_cast<float4*>(out + gaddr) = r;
    }
}

// ---------------------------------------------------------------------------
extern "C" void kernel_launch(void* const* d_in, const int* in_sizes, int n_in,
                              void* d_out, int out_size) {
    const float* x        = (const float*)d_in[0];
    const float* text_emb = (const float*)d_in[1];
    const float* wq       = (const float*)d_in[2];
    const float* bq       = (const float*)d_in[3];
    const float* wk       = (const float*)d_in[4];
    const float* bk       = (const float*)d_in[5];
    const float* wv       = (const float*)d_in[6];
    const float* bv       = (const float*)d_in[7];
    const float* wt       = (const float*)d_in[8];
    const float* bt       = (const float*)d_in[9];
    const float* pos      = (const float*)d_in[10];
    const float* gamma    = (const float*)d_in[11];
    float* out = (float*)d_out;

    cudaFuncSetAttribute(attn_kernel, cudaFuncAttributeMaxDynamicSharedMemorySize, SMEM_BYTES);

    text_bias_kernel<<<1, 256>>>(text_emb, wt, bt);

    const int grid = B_DIM * H_DIM * (W_DIM / WT);  // 2304
    attn_kernel<<<grid, NTHREADS, SMEM_BYTES>>>(x, wq, bq, wk, bk, wv, bv, pos, gamma, out);
}